// round 7
// baseline (speedup 1.0000x reference)
#include <cuda_runtime.h>
#include <cuda_bf16.h>
#include <cstdint>

#define NN 16
#define FULL 0xffffffffu
#define THREADS 128
#define ELEMS 8

// dynamic smem layout (bytes)
#define OFF_ENT   0                       // 8 elems * 32 rows * 256B = 65536
#define OFF_W     65536                   // 16384
#define OFF_REL   (OFF_W + 16384)         // 8192
#define OFF_B     (OFF_REL + 8192)        // 256
#define OFF_USER  (OFF_B + 256)           // 8*16*16 = 2048
#define OFF_COMB  (OFF_USER + 2048)       // 4*34*16 = 2176
#define SMEM_TOTAL (OFF_COMB + 2176)

typedef unsigned long long u64;

__device__ __forceinline__ float fast_tanh(float x) {
    float r;
    asm("tanh.approx.f32 %0, %1;" : "=f"(r) : "f"(x));
    return r;
}
__device__ __forceinline__ unsigned smem_u32(const void* p) {
    return (unsigned)__cvta_generic_to_shared(p);
}
__device__ __forceinline__ void cp16(unsigned dst, const void* src) {
    asm volatile("cp.async.cg.shared.global [%0], [%1], 16;" :: "r"(dst), "l"(src) : "memory");
}
__device__ __forceinline__ u64 pol_evict_first() {
    u64 p;
    asm("createpolicy.fractional.L2::evict_first.b64 %0, 1.0;" : "=l"(p));
    return p;
}
__device__ __forceinline__ int ldg_i_hint(const int* a, u64 pol) {
    int v;
    asm volatile("ld.global.nc.L2::cache_hint.b32 %0, [%1], %2;"
                 : "=r"(v) : "l"(a), "l"(pol));
    return v;
}

__global__ void __launch_bounds__(THREADS) klgcn_kernel(
    const int* __restrict__ u,
    const int* __restrict__ v,
    const int* __restrict__ user_neighbor,
    const int* __restrict__ item_neighbor,
    const int* __restrict__ adj_ent,
    const int* __restrict__ adj_rel,
    const float* __restrict__ usr_emb,
    const float* __restrict__ ent_emb,
    const float* __restrict__ rel_emb,
    const float* __restrict__ agg_W,
    const float* __restrict__ agg_b,
    float* __restrict__ out,
    int batch)
{
    extern __shared__ char smem[];
    float4* const sEnt  = (float4*)(smem + OFF_ENT);   // [el*32+row][hl]
    float4* const sW    = (float4*)(smem + OFF_W);     // [j*16+hl]
    float4* const sRel  = (float4*)(smem + OFF_REL);   // [r*16 + (k+r)&15] rotated
    float4* const sB    = (float4*)(smem + OFF_B);
    float4* const sUser = (float4*)(smem + OFF_USER);  // [el*16+hl]
    float4* const sComb = (float4*)(smem + OFF_COMB);

    const int tid  = threadIdx.x;
    const int lane = tid & 31;
    const int warp = tid >> 5;
    const int half = lane >> 4;
    const int hl   = lane & 15;
    const int hbase = half << 4;
    const int el   = (warp << 1) + half;                   // 0..7 local element
    const int gw   = blockIdx.x * 4 + warp;                // global warp
    int b = (gw << 1) + half;
    const bool valid = (b < batch);
    if (b >= batch) b = batch - 1;

    const u64 PEF = pol_evict_first();
    const float4* __restrict__ usr4 = (const float4*)usr_emb;
    const float4* __restrict__ ent4 = (const float4*)ent_emb;

    // ---- early index loads (one-shot streams: evict_first) ----
    const int uu = ldg_i_hint(u + b, PEF);
    const int vv = ldg_i_hint(v + b, PEF);
    const int in_idx = ldg_i_hint(item_neighbor + b * NN + hl, PEF);
    const int un_idx = ldg_i_hint(user_neighbor + b * NN + hl, PEF);

    // ---- fill W / rel (rotated) / bias into smem ----
    {
        const float4* __restrict__ Wg = (const float4*)agg_W;
        #pragma unroll
        for (int i = 0; i < 8; i++)
            sW[i * 128 + tid] = Wg[i * 128 + tid];
        const float4* __restrict__ Rg = (const float4*)rel_emb;
        #pragma unroll
        for (int i = 0; i < 4; i++) {
            const int idx = i * 128 + tid;       // 0..511
            const int row = idx >> 4, k = idx & 15;
            sRel[row * 16 + ((k + row) & 15)] = Rg[idx];
        }
        if (tid < 16) sB[tid] = ((const float4*)agg_b)[tid];
    }

    // dependent index gathers
    const int ae_idx = __ldg(adj_ent + vv * NN + hl);
    const int ar_idx = __ldg(adj_rel + vv * NN + hl);

    __syncthreads();   // smem tables ready

    // ---- front-batched usr_emb lite gathers into registers ----
    float4 ua[NN];
    #pragma unroll
    for (int n = 0; n < NN; n++) {
        const int i1 = __shfl_sync(FULL, in_idx, hbase + n);
        ua[n] = usr4[i1 * 16 + hl];
    }

    // ---- cp.async staging of ent rows: user_neighbor (rows 0..15) + adj_ent (16..31) ----
    const unsigned entBase = smem_u32(sEnt) + (unsigned)(el * 32) * 256u + (unsigned)(hl << 4);
    #pragma unroll
    for (int n = 0; n < NN; n++) {
        const int i2 = __shfl_sync(FULL, un_idx, hbase + n);
        const int e  = __shfl_sync(FULL, ae_idx, hbase + n);
        const unsigned dstU = entBase + (unsigned)(n * 256);
        cp16(dstU,        (const char*)ent_emb + ((size_t)i2 << 8) + (hl << 4));
        cp16(dstU + 4096, (const char*)ent_emb + ((size_t)e  << 8) + (hl << 4));
    }
    asm volatile("cp.async.commit_group;" ::: "memory");

    // self rows (overlap with cp.async)
    const float4 user_e = usr4[uu * 16 + hl];
    const float4 item_o = ent4[vv * 16 + hl];

    // lite_user accumulate
    float4 lu = make_float4(0.f, 0.f, 0.f, 0.f);
    #pragma unroll
    for (int n = 0; n < NN; n++) {
        lu.x += ua[n].x; lu.y += ua[n].y; lu.z += ua[n].z; lu.w += ua[n].w;
    }

    // publish user row for transposed score computation
    sUser[el * 16 + hl] = user_e;

    asm volatile("cp.async.wait_group 0;" ::: "memory");
    __syncthreads();   // staged ent rows + sUser visible

    // ---- transposed attention scores: lane hl owns neighbor hl ----
    // sc[hl] = <user_row, rel_emb[ar_idx]>  (full 64-dim dot per lane)
    float psc = 0.f;
    {
        const float4* uRow = sUser + el * 16;
        #pragma unroll
        for (int k = 0; k < 16; k++) {
            const float4 uv = uRow[k];
            const float4 rv = sRel[ar_idx * 16 + ((k + ar_idx) & 15)];
            psc += uv.x * rv.x + uv.y * rv.y + uv.z * rv.z + uv.w * rv.w;
        }
    }
    // exp (no max shift: |sc| << 1 for 0.1-scale embeddings), half-wide sum
    const float wexp = __expf(psc);
    float ssum = wexp;
    ssum += __shfl_xor_sync(FULL, ssum, 8);
    ssum += __shfl_xor_sync(FULL, ssum, 4);
    ssum += __shfl_xor_sync(FULL, ssum, 2);
    ssum += __shfl_xor_sync(FULL, ssum, 1);
    const float inv = 1.0f / ssum;

    // ---- lite_item from staged rows + attention aggregation ----
    const float4* eRows = sEnt + el * 32 * 16;   // float4 index base
    float4 li = make_float4(0.f, 0.f, 0.f, 0.f);
    #pragma unroll
    for (int n = 0; n < NN; n++) {
        const float4 c = eRows[n * 16 + hl];
        li.x += c.x; li.y += c.y; li.z += c.z; li.w += c.w;
    }
    float4 agg = make_float4(0.f, 0.f, 0.f, 0.f);
    #pragma unroll
    for (int n = 0; n < NN; n++) {
        const float wn = __shfl_sync(FULL, wexp, hbase + n) * inv;
        const float4 ev = eRows[(16 + n) * 16 + hl];
        agg.x += wn * ev.x; agg.y += wn * ev.y; agg.z += wn * ev.z; agg.w += wn * ev.w;
    }
    float4 comb;
    comb.x = item_o.x + agg.x;
    comb.y = item_o.y + agg.y;
    comb.z = item_o.z + agg.z;
    comb.w = item_o.w + agg.w;

    // ---- item_emb = tanh(combined @ W + bias) via smem broadcast ----
    const int wslot = warp * 34 + half * 17;
    sComb[wslot + hl] = comb;
    __syncwarp();

    float4 acc = sB[hl];
    #pragma unroll
    for (int q = 0; q < 16; q++) {
        const float4 cv = sComb[wslot + q];
        const float4 w0 = sW[(4 * q + 0) * 16 + hl];
        const float4 w1 = sW[(4 * q + 1) * 16 + hl];
        const float4 w2 = sW[(4 * q + 2) * 16 + hl];
        const float4 w3 = sW[(4 * q + 3) * 16 + hl];
        acc.x += cv.x * w0.x + cv.y * w1.x + cv.z * w2.x + cv.w * w3.x;
        acc.y += cv.x * w0.y + cv.y * w1.y + cv.z * w2.y + cv.w * w3.y;
        acc.z += cv.x * w0.z + cv.y * w1.z + cv.z * w2.z + cv.w * w3.z;
        acc.w += cv.x * w0.w + cv.y * w1.w + cv.z * w2.w + cv.w * w3.w;
    }

    // ---- final blend + dot + sigmoid ----
    const float inv_n = 1.0f / (float)NN;
    float p = (0.5f * (lu.x * inv_n) + 0.5f * user_e.x) * (0.5f * (li.x * inv_n) + 0.5f * fast_tanh(acc.x))
            + (0.5f * (lu.y * inv_n) + 0.5f * user_e.y) * (0.5f * (li.y * inv_n) + 0.5f * fast_tanh(acc.y))
            + (0.5f * (lu.z * inv_n) + 0.5f * user_e.z) * (0.5f * (li.z * inv_n) + 0.5f * fast_tanh(acc.z))
            + (0.5f * (lu.w * inv_n) + 0.5f * user_e.w) * (0.5f * (li.w * inv_n) + 0.5f * fast_tanh(acc.w));
    p += __shfl_xor_sync(FULL, p, 8);
    p += __shfl_xor_sync(FULL, p, 4);
    p += __shfl_xor_sync(FULL, p, 2);
    p += __shfl_xor_sync(FULL, p, 1);

    if (hl == 0 && valid) {
        out[b] = 1.0f / (1.0f + __expf(-p));
    }
}

extern "C" void kernel_launch(void* const* d_in, const int* in_sizes, int n_in,
                              void* d_out, int out_size) {
    const int*   u             = (const int*)d_in[0];
    const int*   v             = (const int*)d_in[1];
    const int*   user_neighbor = (const int*)d_in[2];
    const int*   item_neighbor = (const int*)d_in[3];
    const int*   adj_ent       = (const int*)d_in[4];
    const int*   adj_rel       = (const int*)d_in[5];
    const float* usr_emb       = (const float*)d_in[6];
    const float* ent_emb       = (const float*)d_in[7];
    const float* rel_emb       = (const float*)d_in[8];
    const float* agg_W         = (const float*)d_in[9];
    const float* agg_b         = (const float*)d_in[10];
    float*       out           = (float*)d_out;

    const int batch = in_sizes[0];
    cudaFuncSetAttribute(klgcn_kernel,
                         cudaFuncAttributeMaxDynamicSharedMemorySize, SMEM_TOTAL);
    const int blocks = (batch + ELEMS - 1) / ELEMS;
    klgcn_kernel<<<blocks, THREADS, SMEM_TOTAL>>>(
        u, v, user_neighbor, item_neighbor, adj_ent, adj_rel,
        usr_emb, ent_emb, rel_emb, agg_W, agg_b, out, batch);
}

// round 8
// speedup vs baseline: 1.3934x; 1.3934x over previous
#include <cuda_runtime.h>
#include <cuda_bf16.h>
#include <cstdint>

#define NN 16
#define DIM 64
#define FULL 0xffffffffu

typedef unsigned long long u64;

__device__ __forceinline__ float fast_tanh(float x) {
    float r;
    asm("tanh.approx.f32 %0, %1;" : "=f"(r) : "f"(x));
    return r;
}
__device__ __forceinline__ u64 pol_evict_last() {
    u64 p;
    asm("createpolicy.fractional.L2::evict_last.b64 %0, 1.0;" : "=l"(p));
    return p;
}
__device__ __forceinline__ u64 pol_evict_first() {
    u64 p;
    asm("createpolicy.fractional.L2::evict_first.b64 %0, 1.0;" : "=l"(p));
    return p;
}
__device__ __forceinline__ float4 ldg_f4_hint(const float4* a, u64 pol) {
    float4 v;
    asm volatile("ld.global.nc.L2::cache_hint.v4.f32 {%0,%1,%2,%3}, [%4], %5;"
                 : "=f"(v.x), "=f"(v.y), "=f"(v.z), "=f"(v.w)
                 : "l"(a), "l"(pol));
    return v;
}
__device__ __forceinline__ int ldg_i_hint(const int* a, u64 pol) {
    int v;
    asm volatile("ld.global.nc.L2::cache_hint.b32 %0, [%1], %2;"
                 : "=r"(v) : "l"(a), "l"(pol));
    return v;
}
__device__ __forceinline__ void pf2(const char* p) {
    asm volatile("prefetch.global.L2 [%0];" :: "l"(p));
    asm volatile("prefetch.global.L2 [%0];" :: "l"(p + 128));
}

// Half-warp per element; each half-warp processes TWO elements (h and h+H),
// with element 1's rows L2-prefetched before element 0's compute phases.
__global__ void __launch_bounds__(128, 8) klgcn_kernel(
    const int* __restrict__ u,
    const int* __restrict__ v,
    const int* __restrict__ user_neighbor,
    const int* __restrict__ item_neighbor,
    const int* __restrict__ adj_ent,
    const int* __restrict__ adj_rel,
    const float* __restrict__ usr_emb,
    const float* __restrict__ ent_emb,
    const float* __restrict__ rel_emb,
    const float* __restrict__ agg_W,
    const float* __restrict__ agg_b,
    float* __restrict__ out,
    int batch, int H)
{
    __shared__ float4 sW[DIM * 16];    // W[j][4h..4h+3] at sW[j*16+h]
    __shared__ float4 sB[16];
    __shared__ float4 sComb[4 * 34];   // per-warp, halves bank-disjoint

    const int tid = threadIdx.x;
    {   // cooperative load of W + bias
        const float4* __restrict__ Wg = (const float4*)agg_W;
        #pragma unroll
        for (int i = 0; i < 8; i++)
            sW[i * 128 + tid] = Wg[i * 128 + tid];
        if (tid < 16) sB[tid] = ((const float4*)agg_b)[tid];
    }

    const int lane = tid & 31;
    const int warp = tid >> 5;
    const int half = lane >> 4;
    const int hl   = lane & 15;
    const int hbase = half << 4;
    const int h = blockIdx.x * 8 + warp * 2 + half;   // half-warp id

    const u64 PEL = pol_evict_last();
    const u64 PEF = pol_evict_first();

    const float4* __restrict__ usr4 = (const float4*)usr_emb;
    const float4* __restrict__ ent4 = (const float4*)ent_emb;
    const float4* __restrict__ rel4 = (const float4*)rel_emb;

    // ---- all index loads for BOTH elements up front ----
    int bs[2];  bool val[2];
    int uu[2], vv[2], ini[2], uni[2], ae[2], ar[2];
    #pragma unroll
    for (int t = 0; t < 2; t++) {
        int b = h + t * H;
        val[t] = (b < batch);
        if (b >= batch) b = batch - 1;
        bs[t] = b;
        uu[t]  = ldg_i_hint(u + b, PEF);
        vv[t]  = ldg_i_hint(v + b, PEF);
        ini[t] = ldg_i_hint(item_neighbor + b * NN + hl, PEF);
        uni[t] = ldg_i_hint(user_neighbor + b * NN + hl, PEF);
    }
    #pragma unroll
    for (int t = 0; t < 2; t++) {
        ae[t] = ldg_i_hint(adj_ent + vv[t] * NN + hl, PEL);
        ar[t] = ldg_i_hint(adj_rel + vv[t] * NN + hl, PEL);
    }

    // ---- L2 prefetch of element 1's gather rows (covers all 16 rows/half) ----
    pf2((const char*)usr_emb + ((size_t)ini[1] << 8));
    pf2((const char*)ent_emb + ((size_t)uni[1] << 8));
    pf2((const char*)ent_emb + ((size_t)ae[1]  << 8));

    __syncthreads();   // sW/sB ready

    const int wslot = warp * 34 + half * 17;

    #pragma unroll
    for (int t = 0; t < 2; t++) {
        const int b = bs[t];

        const float4 user_e = ldg_f4_hint(usr4 + uu[t] * 16 + hl, PEL);
        const float4 item_o = ent4[vv[t] * 16 + hl];

        // ---- lite_user / lite_item: mean of 16 gathered rows each ----
        float4 lu = make_float4(0.f, 0.f, 0.f, 0.f);
        float4 li = make_float4(0.f, 0.f, 0.f, 0.f);
        #pragma unroll
        for (int n = 0; n < NN; n++) {
            const int i1 = __shfl_sync(FULL, ini[t], hbase + n);
            const int i2 = __shfl_sync(FULL, uni[t], hbase + n);
            const float4 a = ldg_f4_hint(usr4 + i1 * 16 + hl, PEL);
            const float4 c = ent4[i2 * 16 + hl];
            lu.x += a.x; lu.y += a.y; lu.z += a.z; lu.w += a.w;
            li.x += c.x; li.y += c.y; li.z += c.z; li.w += c.w;
        }

        // ---- fused attention: score -> exp (no max shift; 0.1-scale
        // embeddings keep |sc| << 1) -> weighted agg + online sum ----
        float4 agg = make_float4(0.f, 0.f, 0.f, 0.f);
        float ssum = 0.f;
        #pragma unroll
        for (int n = 0; n < NN; n++) {
            const int r = __shfl_sync(FULL, ar[t], hbase + n);
            const int e = __shfl_sync(FULL, ae[t], hbase + n);
            const float4 re = ldg_f4_hint(rel4 + r * 16 + hl, PEL);
            const float4 ev = ent4[e * 16 + hl];
            float p = user_e.x * re.x + user_e.y * re.y + user_e.z * re.z + user_e.w * re.w;
            p += __shfl_xor_sync(FULL, p, 8);
            p += __shfl_xor_sync(FULL, p, 4);
            p += __shfl_xor_sync(FULL, p, 2);
            p += __shfl_xor_sync(FULL, p, 1);
            const float w = __expf(p);
            ssum += w;
            agg.x += w * ev.x; agg.y += w * ev.y; agg.z += w * ev.z; agg.w += w * ev.w;
        }
        const float inv = 1.0f / ssum;
        float4 comb;
        comb.x = item_o.x + agg.x * inv;
        comb.y = item_o.y + agg.y * inv;
        comb.z = item_o.z + agg.z * inv;
        comb.w = item_o.w + agg.w * inv;

        // ---- item_emb = tanh(combined @ W + bias) via smem broadcast ----
        __syncwarp();
        sComb[wslot + hl] = comb;
        __syncwarp();

        float4 acc = sB[hl];
        #pragma unroll
        for (int q = 0; q < 16; q++) {
            const float4 cv = sComb[wslot + q];
            const float4 w0 = sW[(4 * q + 0) * 16 + hl];
            const float4 w1 = sW[(4 * q + 1) * 16 + hl];
            const float4 w2 = sW[(4 * q + 2) * 16 + hl];
            const float4 w3 = sW[(4 * q + 3) * 16 + hl];
            acc.x += cv.x * w0.x + cv.y * w1.x + cv.z * w2.x + cv.w * w3.x;
            acc.y += cv.x * w0.y + cv.y * w1.y + cv.z * w2.y + cv.w * w3.y;
            acc.z += cv.x * w0.z + cv.y * w1.z + cv.z * w2.z + cv.w * w3.z;
            acc.w += cv.x * w0.w + cv.y * w1.w + cv.z * w2.w + cv.w * w3.w;
        }

        // ---- final blend + dot + sigmoid ----
        const float inv_n = 1.0f / (float)NN;
        float p = (0.5f * (lu.x * inv_n) + 0.5f * user_e.x) * (0.5f * (li.x * inv_n) + 0.5f * fast_tanh(acc.x))
                + (0.5f * (lu.y * inv_n) + 0.5f * user_e.y) * (0.5f * (li.y * inv_n) + 0.5f * fast_tanh(acc.y))
                + (0.5f * (lu.z * inv_n) + 0.5f * user_e.z) * (0.5f * (li.z * inv_n) + 0.5f * fast_tanh(acc.z))
                + (0.5f * (lu.w * inv_n) + 0.5f * user_e.w) * (0.5f * (li.w * inv_n) + 0.5f * fast_tanh(acc.w));
        p += __shfl_xor_sync(FULL, p, 8);
        p += __shfl_xor_sync(FULL, p, 4);
        p += __shfl_xor_sync(FULL, p, 2);
        p += __shfl_xor_sync(FULL, p, 1);

        if (hl == 0 && val[t]) {
            out[b] = 1.0f / (1.0f + __expf(-p));
        }
    }
}

extern "C" void kernel_launch(void* const* d_in, const int* in_sizes, int n_in,
                              void* d_out, int out_size) {
    const int*   u             = (const int*)d_in[0];
    const int*   v             = (const int*)d_in[1];
    const int*   user_neighbor = (const int*)d_in[2];
    const int*   item_neighbor = (const int*)d_in[3];
    const int*   adj_ent       = (const int*)d_in[4];
    const int*   adj_rel       = (const int*)d_in[5];
    const float* usr_emb       = (const float*)d_in[6];
    const float* ent_emb       = (const float*)d_in[7];
    const float* rel_emb       = (const float*)d_in[8];
    const float* agg_W         = (const float*)d_in[9];
    const float* agg_b         = (const float*)d_in[10];
    float*       out           = (float*)d_out;

    const int batch = in_sizes[0];
    const int H = (batch + 1) / 2;          // halves per pass
    const int blocks = (H + 7) / 8;         // 8 half-warps per block
    klgcn_kernel<<<blocks, 128>>>(u, v, user_neighbor, item_neighbor,
                                  adj_ent, adj_rel, usr_emb, ent_emb,
                                  rel_emb, agg_W, agg_b, out, batch, H);
}

// round 9
// speedup vs baseline: 1.5708x; 1.1273x over previous
#include <cuda_runtime.h>
#include <cuda_bf16.h>
#include <cstdint>

#define NN 16
#define DIM 64
#define FULL 0xffffffffu
#define CSTRIDE 68   // float stride for per-element comb/item rows (bank-disjoint)

typedef unsigned long long u64;

__device__ __forceinline__ float fast_tanh(float x) {
    float r;
    asm("tanh.approx.f32 %0, %1;" : "=f"(r) : "f"(x));
    return r;
}
__device__ __forceinline__ u64 pol_evict_last() {
    u64 p;
    asm("createpolicy.fractional.L2::evict_last.b64 %0, 1.0;" : "=l"(p));
    return p;
}
__device__ __forceinline__ u64 pol_evict_first() {
    u64 p;
    asm("createpolicy.fractional.L2::evict_first.b64 %0, 1.0;" : "=l"(p));
    return p;
}
__device__ __forceinline__ float4 ldg_f4_hint(const float4* a, u64 pol) {
    float4 v;
    asm volatile("ld.global.nc.L2::cache_hint.v4.f32 {%0,%1,%2,%3}, [%4], %5;"
                 : "=f"(v.x), "=f"(v.y), "=f"(v.z), "=f"(v.w)
                 : "l"(a), "l"(pol));
    return v;
}
__device__ __forceinline__ int ldg_i_hint(const int* a, u64 pol) {
    int v;
    asm volatile("ld.global.nc.L2::cache_hint.b32 %0, [%1], %2;"
                 : "=r"(v) : "l"(a), "l"(pol));
    return v;
}
__device__ __forceinline__ void pf2(const char* p) {
    asm volatile("prefetch.global.L2 [%0];" :: "l"(p));
    asm volatile("prefetch.global.L2 [%0];" :: "l"(p + 128));
}

// Half-warp per element for gathers/attention; block-cooperative matvec
// reuses W 8x across the block's elements.
__global__ void __launch_bounds__(128, 8) klgcn_kernel(
    const int* __restrict__ u,
    const int* __restrict__ v,
    const int* __restrict__ user_neighbor,
    const int* __restrict__ item_neighbor,
    const int* __restrict__ adj_ent,
    const int* __restrict__ adj_rel,
    const float* __restrict__ usr_emb,
    const float* __restrict__ ent_emb,
    const float* __restrict__ rel_emb,
    const float* __restrict__ agg_W,
    const float* __restrict__ agg_b,
    float* __restrict__ out,
    int batch)
{
    __shared__ float4 sW[DIM * 16];        // W[j][4q..4q+3] at sW[j*16+q]  (16 KB)
    __shared__ float4 sB[16];
    __shared__ float  sComb[8 * CSTRIDE];  // comb[el][j] at el*68+j
    __shared__ float  sItem[8 * CSTRIDE];  // tanh result, same layout

    const int tid = threadIdx.x;
    {   // cooperative load of W + bias
        const float4* __restrict__ Wg = (const float4*)agg_W;
        #pragma unroll
        for (int i = 0; i < 8; i++)
            sW[i * 128 + tid] = Wg[i * 128 + tid];
        if (tid < 16) sB[tid] = ((const float4*)agg_b)[tid];
    }

    const int lane = tid & 31;
    const int warp = tid >> 5;
    const int half = lane >> 4;
    const int hl   = lane & 15;
    const int hbase = half << 4;
    const int el   = (warp << 1) + half;          // 0..7
    int b = blockIdx.x * 8 + el;
    const bool valid = (b < batch);
    if (b >= batch) b = batch - 1;

    const u64 PEL = pol_evict_last();
    const u64 PEF = pol_evict_first();

    const float4* __restrict__ usr4 = (const float4*)usr_emb;
    const float4* __restrict__ ent4 = (const float4*)ent_emb;
    const float4* __restrict__ rel4 = (const float4*)rel_emb;

    // ---- early index loads ----
    const int uu = ldg_i_hint(u + b, PEF);
    const int vv = ldg_i_hint(v + b, PEF);
    const int in_idx = ldg_i_hint(item_neighbor + b * NN + hl, PEF);
    const int un_idx = ldg_i_hint(user_neighbor + b * NN + hl, PEF);
    const int ae_idx = ldg_i_hint(adj_ent + vv * NN + hl, PEL);
    const int ar_idx = ldg_i_hint(adj_rel + vv * NN + hl, PEL);

    // prefetch the latest-used gather rows (attention ent rows)
    pf2((const char*)ent_emb + ((size_t)ae_idx << 8));

    const float4 user_e = ldg_f4_hint(usr4 + uu * 16 + hl, PEL);
    const float4 item_o = ent4[vv * 16 + hl];

    // ---- lite_user / lite_item: mean of 16 gathered rows each ----
    float4 lu = make_float4(0.f, 0.f, 0.f, 0.f);
    float4 li = make_float4(0.f, 0.f, 0.f, 0.f);
    #pragma unroll
    for (int n = 0; n < NN; n++) {
        const int i1 = __shfl_sync(FULL, in_idx, hbase + n);
        const int i2 = __shfl_sync(FULL, un_idx, hbase + n);
        const float4 a = ldg_f4_hint(usr4 + i1 * 16 + hl, PEL);
        const float4 c = ent4[i2 * 16 + hl];
        lu.x += a.x; lu.y += a.y; lu.z += a.z; lu.w += a.w;
        li.x += c.x; li.y += c.y; li.z += c.z; li.w += c.w;
    }

    // ---- fused attention: score -> exp (no max shift; 0.1-scale embeddings
    // keep |sc| << 1) -> weighted aggregation + online sum ----
    float4 agg = make_float4(0.f, 0.f, 0.f, 0.f);
    float ssum = 0.f;
    #pragma unroll
    for (int n = 0; n < NN; n++) {
        const int r = __shfl_sync(FULL, ar_idx, hbase + n);
        const int e = __shfl_sync(FULL, ae_idx, hbase + n);
        const float4 re = ldg_f4_hint(rel4 + r * 16 + hl, PEL);
        const float4 ev = ent4[e * 16 + hl];
        float p = user_e.x * re.x + user_e.y * re.y + user_e.z * re.z + user_e.w * re.w;
        p += __shfl_xor_sync(FULL, p, 8);
        p += __shfl_xor_sync(FULL, p, 4);
        p += __shfl_xor_sync(FULL, p, 2);
        p += __shfl_xor_sync(FULL, p, 1);
        const float w = __expf(p);
        ssum += w;
        agg.x += w * ev.x; agg.y += w * ev.y; agg.z += w * ev.z; agg.w += w * ev.w;
    }
    const float inv = 1.0f / ssum;
    float4 comb;
    comb.x = item_o.x + agg.x * inv;
    comb.y = item_o.y + agg.y * inv;
    comb.z = item_o.z + agg.z * inv;
    comb.w = item_o.w + agg.w * inv;

    // publish comb for the cooperative matvec
    *(float4*)(sComb + el * CSTRIDE + 4 * hl) = comb;
    __syncthreads();

    // ---- block-cooperative matvec: out[el][4q..4q+3] = b + comb[el] @ W ----
    // warp w, lane l: el2 = l>>2 (8 elements), q = (l&3) + 4w (dim group 0..15)
    {
        const int el2 = lane >> 2;
        const int q   = (lane & 3) + (warp << 2);
        const float* cRow = sComb + el2 * CSTRIDE;
        float4 acc = sB[q];
        #pragma unroll 8
        for (int j = 0; j < DIM; j++) {
            const float  c  = cRow[j];
            const float4 wj = sW[j * 16 + q];
            acc.x += c * wj.x; acc.y += c * wj.y;
            acc.z += c * wj.z; acc.w += c * wj.w;
        }
        float4 it;
        it.x = fast_tanh(acc.x); it.y = fast_tanh(acc.y);
        it.z = fast_tanh(acc.z); it.w = fast_tanh(acc.w);
        *(float4*)(sItem + el2 * CSTRIDE + 4 * q) = it;
    }
    __syncthreads();

    // ---- final blend + dot + sigmoid (back in half-warp layout) ----
    const float4 item_e = *(const float4*)(sItem + el * CSTRIDE + 4 * hl);
    const float inv_n = 1.0f / (float)NN;
    float p = (0.5f * (lu.x * inv_n) + 0.5f * user_e.x) * (0.5f * (li.x * inv_n) + 0.5f * item_e.x)
            + (0.5f * (lu.y * inv_n) + 0.5f * user_e.y) * (0.5f * (li.y * inv_n) + 0.5f * item_e.y)
            + (0.5f * (lu.z * inv_n) + 0.5f * user_e.z) * (0.5f * (li.z * inv_n) + 0.5f * item_e.z)
            + (0.5f * (lu.w * inv_n) + 0.5f * user_e.w) * (0.5f * (li.w * inv_n) + 0.5f * item_e.w);
    p += __shfl_xor_sync(FULL, p, 8);
    p += __shfl_xor_sync(FULL, p, 4);
    p += __shfl_xor_sync(FULL, p, 2);
    p += __shfl_xor_sync(FULL, p, 1);

    if (hl == 0 && valid) {
        out[b] = 1.0f / (1.0f + __expf(-p));
    }
}

extern "C" void kernel_launch(void* const* d_in, const int* in_sizes, int n_in,
                              void* d_out, int out_size) {
    const int*   u             = (const int*)d_in[0];
    const int*   v             = (const int*)d_in[1];
    const int*   user_neighbor = (const int*)d_in[2];
    const int*   item_neighbor = (const int*)d_in[3];
    const int*   adj_ent       = (const int*)d_in[4];
    const int*   adj_rel       = (const int*)d_in[5];
    const float* usr_emb       = (const float*)d_in[6];
    const float* ent_emb       = (const float*)d_in[7];
    const float* rel_emb       = (const float*)d_in[8];
    const float* agg_W         = (const float*)d_in[9];
    const float* agg_b         = (const float*)d_in[10];
    float*       out           = (float*)d_out;

    const int batch = in_sizes[0];
    const int blocks = (batch + 7) / 8;
    klgcn_kernel<<<blocks, 128>>>(u, v, user_neighbor, item_neighbor,
                                  adj_ent, adj_rel, usr_emb, ent_emb,
                                  rel_emb, agg_W, agg_b, out, batch);
}

// round 10
// speedup vs baseline: 1.6875x; 1.0743x over previous
#include <cuda_runtime.h>
#include <cuda_bf16.h>
#include <cstdint>

#define NN 16
#define DIM 64
#define FULL 0xffffffffu
#define ELEMS 16
#define THREADS 256
#define CSTRIDE 68   // float stride for comb/item rows (16B-aligned, near-conflict-free)

typedef unsigned long long u64;

__device__ __forceinline__ float fast_tanh(float x) {
    float r;
    asm("tanh.approx.f32 %0, %1;" : "=f"(r) : "f"(x));
    return r;
}
__device__ __forceinline__ u64 pol_evict_last() {
    u64 p;
    asm("createpolicy.fractional.L2::evict_last.b64 %0, 1.0;" : "=l"(p));
    return p;
}
__device__ __forceinline__ u64 pol_evict_first() {
    u64 p;
    asm("createpolicy.fractional.L2::evict_first.b64 %0, 1.0;" : "=l"(p));
    return p;
}
__device__ __forceinline__ float4 ldg_f4_hint(const float4* a, u64 pol) {
    float4 v;
    asm volatile("ld.global.nc.L2::cache_hint.v4.f32 {%0,%1,%2,%3}, [%4], %5;"
                 : "=f"(v.x), "=f"(v.y), "=f"(v.z), "=f"(v.w)
                 : "l"(a), "l"(pol));
    return v;
}
__device__ __forceinline__ int ldg_i_hint(const int* a, u64 pol) {
    int v;
    asm volatile("ld.global.nc.L2::cache_hint.b32 %0, [%1], %2;"
                 : "=r"(v) : "l"(a), "l"(pol));
    return v;
}
__device__ __forceinline__ void pf2(const char* p) {
    asm volatile("prefetch.global.L2 [%0];" :: "l"(p));
    asm volatile("prefetch.global.L2 [%0];" :: "l"(p + 128));
}

__global__ void __launch_bounds__(THREADS) klgcn_kernel(
    const int* __restrict__ u,
    const int* __restrict__ v,
    const int* __restrict__ user_neighbor,
    const int* __restrict__ item_neighbor,
    const int* __restrict__ adj_ent,
    const int* __restrict__ adj_rel,
    const float* __restrict__ usr_emb,
    const float* __restrict__ ent_emb,
    const float* __restrict__ rel_emb,
    const float* __restrict__ agg_W,
    const float* __restrict__ agg_b,
    float* __restrict__ out,
    int batch)
{
    __shared__ float4 sW[DIM * 16];            // 16 KB: W[j][4q..] at sW[j*16+q]
    __shared__ float4 sB[16];
    __shared__ float4 sRel[32 * 16];           // 8 KB, rotated: [r*16 + (k+r)&15]
    __shared__ float4 sUser[ELEMS * 17];       // user row per element, padded
    __shared__ float  sComb[ELEMS * CSTRIDE];
    __shared__ float  sItem[ELEMS * CSTRIDE];

    const int tid = threadIdx.x;
    {   // cooperative smem fills
        const float4* __restrict__ Wg = (const float4*)agg_W;
        #pragma unroll
        for (int i = 0; i < 4; i++)
            sW[i * 256 + tid] = Wg[i * 256 + tid];
        const float4* __restrict__ Rg = (const float4*)rel_emb;
        #pragma unroll
        for (int i = 0; i < 2; i++) {
            const int idx = i * 256 + tid;     // 0..511
            const int row = idx >> 4, k = idx & 15;
            sRel[row * 16 + ((k + row) & 15)] = Rg[idx];
        }
        if (tid < 16) sB[tid] = ((const float4*)agg_b)[tid];
    }

    const int lane = tid & 31;
    const int warp = tid >> 5;
    const int half = lane >> 4;
    const int hl   = lane & 15;
    const int hbase = half << 4;
    const int el   = (warp << 1) + half;          // 0..15
    int b = blockIdx.x * ELEMS + el;
    const bool valid = (b < batch);
    if (b >= batch) b = batch - 1;

    const u64 PEL = pol_evict_last();
    const u64 PEF = pol_evict_first();

    const float4* __restrict__ usr4 = (const float4*)usr_emb;
    const float4* __restrict__ ent4 = (const float4*)ent_emb;

    // ---- early index loads ----
    const int uu = ldg_i_hint(u + b, PEF);
    const int vv = ldg_i_hint(v + b, PEF);
    const int in_idx = ldg_i_hint(item_neighbor + b * NN + hl, PEF);
    const int un_idx = ldg_i_hint(user_neighbor + b * NN + hl, PEF);
    const int ae_idx = ldg_i_hint(adj_ent + vv * NN + hl, PEL);
    const int ar_idx = ldg_i_hint(adj_rel + vv * NN + hl, PEL);

    // prefetch the attention ent rows (used last)
    pf2((const char*)ent_emb + ((size_t)ae_idx << 8));

    const float4 user_e = ldg_f4_hint(usr4 + uu * 16 + hl, PEL);
    const float4 item_o = ent4[vv * 16 + hl];

    // publish user row for transposed score computation (same half writes+reads)
    sUser[el * 17 + hl] = user_e;

    // ---- lite_user / lite_item: mean of 16 gathered rows each ----
    float4 lu = make_float4(0.f, 0.f, 0.f, 0.f);
    float4 li = make_float4(0.f, 0.f, 0.f, 0.f);
    #pragma unroll
    for (int n = 0; n < NN; n++) {
        const int i1 = __shfl_sync(FULL, in_idx, hbase + n);
        const int i2 = __shfl_sync(FULL, un_idx, hbase + n);
        const float4 a = ldg_f4_hint(usr4 + i1 * 16 + hl, PEL);
        const float4 c = ent4[i2 * 16 + hl];
        lu.x += a.x; lu.y += a.y; lu.z += a.z; lu.w += a.w;
        li.x += c.x; li.y += c.y; li.z += c.z; li.w += c.w;
    }

    __syncthreads();   // sRel / sW / sB ready (sUser needs only warp scope)

    // ---- transposed attention scores: lane hl owns neighbor hl ----
    float psc = 0.f;
    {
        const float4* uRow = sUser + el * 17;
        #pragma unroll
        for (int k = 0; k < 16; k++) {
            const float4 uv = uRow[k];                             // broadcast
            const float4 rv = sRel[ar_idx * 16 + ((k + ar_idx) & 15)];
            psc += uv.x * rv.x + uv.y * rv.y + uv.z * rv.z + uv.w * rv.w;
        }
    }
    // exp without max shift (0.1-scale embeddings keep |sc| << 1)
    const float wexp = __expf(psc);
    float ssum = wexp;
    ssum += __shfl_xor_sync(FULL, ssum, 8);
    ssum += __shfl_xor_sync(FULL, ssum, 4);
    ssum += __shfl_xor_sync(FULL, ssum, 2);
    ssum += __shfl_xor_sync(FULL, ssum, 1);
    const float inv = 1.0f / ssum;

    // ---- attention-weighted aggregation ----
    float4 agg = make_float4(0.f, 0.f, 0.f, 0.f);
    #pragma unroll
    for (int n = 0; n < NN; n++) {
        const int   e  = __shfl_sync(FULL, ae_idx, hbase + n);
        const float wn = __shfl_sync(FULL, wexp,  hbase + n) * inv;
        const float4 ev = ent4[e * 16 + hl];
        agg.x += wn * ev.x; agg.y += wn * ev.y; agg.z += wn * ev.z; agg.w += wn * ev.w;
    }
    float4 comb;
    comb.x = item_o.x + agg.x;
    comb.y = item_o.y + agg.y;
    comb.z = item_o.z + agg.z;
    comb.w = item_o.w + agg.w;

    // publish comb for the cooperative matvec
    *(float4*)(sComb + el * CSTRIDE + 4 * hl) = comb;
    __syncthreads();

    // ---- block-cooperative matvec: 16-way W reuse ----
    // lane l, warp w: el2 = l>>1 (16 elements), q = (l&1) + 2w (dim group 0..15)
    {
        const int el2 = lane >> 1;
        const int q   = (lane & 1) + (warp << 1);
        const float* cRow = sComb + el2 * CSTRIDE;
        float4 acc = sB[q];
        #pragma unroll 8
        for (int j = 0; j < DIM; j++) {
            const float  c  = cRow[j];
            const float4 wj = sW[j * 16 + q];
            acc.x += c * wj.x; acc.y += c * wj.y;
            acc.z += c * wj.z; acc.w += c * wj.w;
        }
        float4 it;
        it.x = fast_tanh(acc.x); it.y = fast_tanh(acc.y);
        it.z = fast_tanh(acc.z); it.w = fast_tanh(acc.w);
        *(float4*)(sItem + el2 * CSTRIDE + 4 * q) = it;
    }
    __syncthreads();

    // ---- final blend + dot + sigmoid ----
    const float4 item_e = *(const float4*)(sItem + el * CSTRIDE + 4 * hl);
    const float inv_n = 1.0f / (float)NN;
    float p = (0.5f * (lu.x * inv_n) + 0.5f * user_e.x) * (0.5f * (li.x * inv_n) + 0.5f * item_e.x)
            + (0.5f * (lu.y * inv_n) + 0.5f * user_e.y) * (0.5f * (li.y * inv_n) + 0.5f * item_e.y)
            + (0.5f * (lu.z * inv_n) + 0.5f * user_e.z) * (0.5f * (li.z * inv_n) + 0.5f * item_e.z)
            + (0.5f * (lu.w * inv_n) + 0.5f * user_e.w) * (0.5f * (li.w * inv_n) + 0.5f * item_e.w);
    p += __shfl_xor_sync(FULL, p, 8);
    p += __shfl_xor_sync(FULL, p, 4);
    p += __shfl_xor_sync(FULL, p, 2);
    p += __shfl_xor_sync(FULL, p, 1);

    if (hl == 0 && valid) {
        out[b] = 1.0f / (1.0f + __expf(-p));
    }
}

extern "C" void kernel_launch(void* const* d_in, const int* in_sizes, int n_in,
                              void* d_out, int out_size) {
    const int*   u             = (const int*)d_in[0];
    const int*   v             = (const int*)d_in[1];
    const int*   user_neighbor = (const int*)d_in[2];
    const int*   item_neighbor = (const int*)d_in[3];
    const int*   adj_ent       = (const int*)d_in[4];
    const int*   adj_rel       = (const int*)d_in[5];
    const float* usr_emb       = (const float*)d_in[6];
    const float* ent_emb       = (const float*)d_in[7];
    const float* rel_emb       = (const float*)d_in[8];
    const float* agg_W         = (const float*)d_in[9];
    const float* agg_b         = (const float*)d_in[10];
    float*       out           = (float*)d_out;

    const int batch = in_sizes[0];
    const int blocks = (batch + ELEMS - 1) / ELEMS;
    klgcn_kernel<<<blocks, THREADS>>>(u, v, user_neighbor, item_neighbor,
                                      adj_ent, adj_rel, usr_emb, ent_emb,
                                      rel_emb, agg_W, agg_b, out, batch);
}